// round 6
// baseline (speedup 1.0000x reference)
#include <cuda_runtime.h>

#define NN 100000
#define EE 1600000
#define CAP 64          // max in-degree (Poisson(16): P(exceed) ~ 1e-19)
#define FULLM 0xffffffffu
#define NB 592          // persistent blocks (4/SM)

// ---------------- scratch ---------------------------------------------------
__device__ int    g_cnt[NN];            // in-degree
__device__ int    g_slot[NN * CAP];     // src ids: slot[n*CAP + j], j < cnt[n]
__device__ float4 g_bufA4[NN * 4];      // ping (max padded C = 16)
__device__ float4 g_bufB4[NN * 4];      // pong
__device__ float  g_stats[192];         // 3 layers x (32 sum + 32 sumsq)

// ---------------- bucket fill: one pass, row-major slots ---------------------
__global__ void k_fill(const int* __restrict__ ei) {
    int e = blockIdx.x * blockDim.x + threadIdx.x;
    if (e >= EE) return;
    int s = ei[e];
    int d = ei[EE + e];
    int pos = atomicAdd(&g_cnt[d], 1);
    if (pos < CAP) g_slot[d * CAP + pos] = s;
}

// ---------------- per-node epilogue (warp-collective) ------------------------
template <int CI, int CO, int CPI, int CPO, bool LAST>
__device__ __forceinline__ void finish_node(
    int n, int deg, float4 acc, float4 xc, int lane,
    const float* s_wl, const float* s_wr, const float* s_bias,
    float* __restrict__ y, float& lsum, float& lsq)
{
    constexpr int V = CPI / 4;
    // butterfly over edge-groups: lanes with same (lane % V) share a chunk
#pragma unroll
    for (int off = V; off < 32; off <<= 1) {
        acc.x += __shfl_xor_sync(FULLM, acc.x, off);
        acc.y += __shfl_xor_sync(FULLM, acc.y, off);
        acc.z += __shfl_xor_sync(FULLM, acc.z, off);
        acc.w += __shfl_xor_sync(FULLM, acc.w, off);
    }
    float cinv = 1.0f / (float)max(deg, 1);
    float av[CI], xv[CI];
#pragma unroll
    for (int c = 0; c < V; c++) {
        float4 t, u;
        t.x = __shfl_sync(FULLM, acc.x, c); u.x = __shfl_sync(FULLM, xc.x, c);
        t.y = __shfl_sync(FULLM, acc.y, c); u.y = __shfl_sync(FULLM, xc.y, c);
        t.z = __shfl_sync(FULLM, acc.z, c); u.z = __shfl_sync(FULLM, xc.z, c);
        t.w = __shfl_sync(FULLM, acc.w, c); u.w = __shfl_sync(FULLM, xc.w, c);
        if (4 * c + 0 < CI) { av[4 * c + 0] = t.x * cinv; xv[4 * c + 0] = u.x; }
        if (4 * c + 1 < CI) { av[4 * c + 1] = t.y * cinv; xv[4 * c + 1] = u.y; }
        if (4 * c + 2 < CI) { av[4 * c + 2] = t.z * cinv; xv[4 * c + 2] = u.z; }
        if (4 * c + 3 < CI) { av[4 * c + 3] = t.w * cinv; xv[4 * c + 3] = u.w; }
    }
    // lane co computes output channel co
    float o = 0.0f;
    if (lane < CO) {
        o = s_bias[lane];
#pragma unroll
        for (int i = 0; i < CI; i++) {
            o = fmaf(av[i], s_wl[lane * CI + i], o);
            o = fmaf(xv[i], s_wr[lane * CI + i], o);
        }
    }
    float ss = o * o;
#pragma unroll
    for (int off = 16; off; off >>= 1)
        ss += __shfl_xor_sync(FULLM, ss, off);
    float inv = 1.0f / fmaxf(sqrtf(ss), 1e-12f);
    o = fmaxf(o * inv, 0.0f);                       // L2 norm then relu (0 for pad lanes)
    if (lane < CPO) y[(size_t)n * CPO + lane] = o;  // coalesced row store
    if (!LAST) { lsum += o; lsq += o * o; }         // per-lane channel stats
}

// ---------------- fused layer (warp-per-node, persistent, 2-node ILP) --------
template <int CI, int CO, int CPI, int CPO, bool LAST, bool HAS_BN,
          int SIN, int SOUT>
__global__ void node_kernel(const float4* __restrict__ x4,
                            const float* __restrict__ wl,
                            const float* __restrict__ bl,
                            const float* __restrict__ wr,
                            const float* __restrict__ bn_g,
                            const float* __restrict__ bn_b,
                            float* __restrict__ y) {
    constexpr int V = CPI / 4;      // float4 chunks per input row
    constexpr int K = 32 / V;       // edges gathered per round
    __shared__ float s_wl[CO * CI], s_wr[CO * CI], s_bias[CO];
    __shared__ float s_sc[CI], s_sh[CI];
    __shared__ float s_sum[CO], s_sq[CO];

    if (HAS_BN) {
        if (threadIdx.x < CI) {
            int c = threadIdx.x;
            float m  = g_stats[SIN + c] * (1.0f / NN);
            float v  = g_stats[SIN + 32 + c] * (1.0f / NN) - m * m;
            float sc = bn_g[c] * rsqrtf(v + 1e-5f);
            s_sc[c] = sc;
            s_sh[c] = bn_b[c] - m * sc;
        }
        __syncthreads();
    }
    for (int i = threadIdx.x; i < CO * CI; i += blockDim.x) {
        float sc = HAS_BN ? s_sc[i % CI] : 1.0f;
        s_wl[i] = wl[i] * sc;
        s_wr[i] = wr[i] * sc;
    }
    if (threadIdx.x < CO) {
        int co = threadIdx.x;
        float b = bl[co];
        if (HAS_BN) {
#pragma unroll
            for (int i = 0; i < CI; i++)
                b += s_sh[i] * (wl[co * CI + i] + wr[co * CI + i]);
        }
        s_bias[co] = b;
        if (!LAST) { s_sum[co] = 0.0f; s_sq[co] = 0.0f; }
    }
    __syncthreads();

    const int lane   = threadIdx.x & 31;
    const int wid    = (blockIdx.x * blockDim.x + threadIdx.x) >> 5;
    const int nwarp  = (gridDim.x * blockDim.x) >> 5;
    const int e_lane = lane / V;    // which edge slot this lane serves
    const int c_lane = lane % V;    // which row chunk this lane loads

    float lsum = 0.0f, lsq = 0.0f;

    for (int n0 = wid; n0 < NN; n0 += 2 * nwarp) {
        int  n1 = n0 + nwarp;
        bool h1 = (n1 < NN);                      // warp-uniform
        int  deg0 = min(g_cnt[n0], CAP);
        int  deg1 = h1 ? min(g_cnt[n1], CAP) : 0;
        int  dmax = max(deg0, deg1);

        float4 acc0 = make_float4(0.f, 0.f, 0.f, 0.f);
        float4 acc1 = make_float4(0.f, 0.f, 0.f, 0.f);
        float4 xc0  = make_float4(0.f, 0.f, 0.f, 0.f);
        float4 xc1  = make_float4(0.f, 0.f, 0.f, 0.f);
        if (lane < V) {
            xc0 = x4[(size_t)n0 * V + lane];
            if (h1) xc1 = x4[(size_t)n1 * V + lane];
        }

        for (int base = 0; base < dmax; base += K) {
            int e = base + e_lane;
            int s0 = (e < deg0) ? g_slot[n0 * CAP + e] : -1;
            int s1 = (e < deg1) ? g_slot[n1 * CAP + e] : -1;
            if (s0 >= 0) {
                float4 a = x4[(size_t)s0 * V + c_lane];
                acc0.x += a.x; acc0.y += a.y; acc0.z += a.z; acc0.w += a.w;
            }
            if (s1 >= 0) {
                float4 a = x4[(size_t)s1 * V + c_lane];
                acc1.x += a.x; acc1.y += a.y; acc1.z += a.z; acc1.w += a.w;
            }
        }

        finish_node<CI, CO, CPI, CPO, LAST>(n0, deg0, acc0, xc0, lane,
                                            s_wl, s_wr, s_bias, y, lsum, lsq);
        if (h1)
            finish_node<CI, CO, CPI, CPO, LAST>(n1, deg1, acc1, xc1, lane,
                                                s_wl, s_wr, s_bias, y, lsum, lsq);
    }

    if (!LAST) {
        if (lane < CO) {
            atomicAdd(&s_sum[lane], lsum);
            atomicAdd(&s_sq[lane], lsq);
        }
        __syncthreads();
        if (threadIdx.x < CO) {
            atomicAdd(&g_stats[SOUT + threadIdx.x], s_sum[threadIdx.x]);
            atomicAdd(&g_stats[SOUT + 32 + threadIdx.x], s_sq[threadIdx.x]);
        }
    }
}

// ---------------- launch ----------------------------------------------------
extern "C" void kernel_launch(void* const* d_in, const int* in_sizes, int n_in,
                              void* d_out, int out_size) {
    const float* x   = (const float*)d_in[0];
    const int*   ei  = (const int*)d_in[1];     // int32 edge_index (JAX x64 off)
    const float* w1l = (const float*)d_in[2];
    const float* b1l = (const float*)d_in[3];
    const float* w1r = (const float*)d_in[4];
    const float* w2l = (const float*)d_in[5];
    const float* b2l = (const float*)d_in[6];
    const float* w2r = (const float*)d_in[7];
    const float* w3l = (const float*)d_in[8];
    const float* b3l = (const float*)d_in[9];
    const float* w3r = (const float*)d_in[10];
    const float* w4l = (const float*)d_in[11];
    const float* b4l = (const float*)d_in[12];
    const float* w4r = (const float*)d_in[13];
    const float* g1  = (const float*)d_in[14];
    const float* be1 = (const float*)d_in[15];
    const float* g2  = (const float*)d_in[16];
    const float* be2 = (const float*)d_in[17];
    const float* g3  = (const float*)d_in[18];
    const float* be3 = (const float*)d_in[19];
    float* out = (float*)d_out;

    void *p_cnt, *p_stats, *p_bufA, *p_bufB;
    cudaGetSymbolAddress(&p_cnt, g_cnt);
    cudaGetSymbolAddress(&p_stats, g_stats);
    cudaGetSymbolAddress(&p_bufA, g_bufA4);
    cudaGetSymbolAddress(&p_bufB, g_bufB4);
    float* bufA = (float*)p_bufA;
    float* bufB = (float*)p_bufB;

    const int TB = 256;
    const int gridE = (EE + TB - 1) / TB;

    cudaMemsetAsync(p_cnt, 0, NN * sizeof(int));
    cudaMemsetAsync(p_stats, 0, 192 * sizeof(float));
    k_fill<<<gridE, TB>>>(ei);

    // L1: 4 -> 6 (pad 8), no input BN
    node_kernel<4, 6, 4, 8, false, false, 0, 0>
        <<<NB, TB>>>((const float4*)x, w1l, b1l, w1r, nullptr, nullptr, bufA);

    // L2: 6 (pad 8) -> 8, BN1 folded
    node_kernel<6, 8, 8, 8, false, true, 0, 64>
        <<<NB, TB>>>((const float4*)bufA, w2l, b2l, w2r, g1, be1, bufB);

    // L3: 8 -> 16, BN2 folded
    node_kernel<8, 16, 8, 16, false, true, 64, 128>
        <<<NB, TB>>>((const float4*)bufB, w3l, b3l, w3r, g2, be2, bufA);

    // L4: 16 -> 32, BN3 folded, final relu straight to d_out
    node_kernel<16, 32, 16, 32, true, true, 128, 0>
        <<<NB, TB>>>((const float4*)bufA, w4l, b4l, w4r, g3, be3, out);
}

// round 7
// speedup vs baseline: 1.4903x; 1.4903x over previous
#include <cuda_runtime.h>

#define NN 100000
#define EE 1600000
#define CAP 64   // max in-degree bucket capacity (Poisson(16): P(exceed) ~ 1e-19)

// ---------------- scratch ---------------------------------------------------
__device__ int    g_cnt[NN];           // in-degree
__device__ int    g_slot[CAP * NN];    // src ids: slot[j*NN + dst], j < cnt[dst]
__device__ float4 g_bufA4[NN * 4];     // ping (max padded C = 16)
__device__ float4 g_bufB4[NN * 4];     // pong
__device__ float  g_stats[192];        // 3 layers x (32 sum + 32 sumsq)

// ---------------- bucket fill: one pass, column-major slots ------------------
__global__ void k_fill(const int* __restrict__ ei) {
    int e = blockIdx.x * blockDim.x + threadIdx.x;
    if (e >= EE) return;
    int s = ei[e];
    int d = ei[EE + e];
    int pos = atomicAdd(&g_cnt[d], 1);
    if (pos < CAP) g_slot[pos * NN + d] = s;
}

// ---------------- fused layer -----------------------------------------------
// gather-mean + (BN folded into weights) + lin_l + lin_r + L2norm + relu
// (+ BN partial sums for the NEXT layer unless LAST)
template <int CI, int CO, int CPI, int CPO, bool LAST, bool HAS_BN,
          int SIN, int SOUT>
__global__ void node_kernel(const float4* __restrict__ x4,
                            const float* __restrict__ wl,
                            const float* __restrict__ bl,
                            const float* __restrict__ wr,
                            const float* __restrict__ bn_g,
                            const float* __restrict__ bn_b,
                            float* __restrict__ y) {
    constexpr int V = CPI / 4;
    constexpr int W = CPO / 4;
    constexpr int U = (V <= 2) ? 4 : 2;      // edge unroll (reg-pressure capped)
    __shared__ float s_wl[CO * CI];
    __shared__ float s_wr[CO * CI];
    __shared__ float s_bias[CO];
    __shared__ float s_sc[CI], s_sh[CI];
    __shared__ float s_sum[CO];
    __shared__ float s_sq[CO];

    if (HAS_BN) {
        if (threadIdx.x < CI) {
            int c = threadIdx.x;
            float m  = g_stats[SIN + c] * (1.0f / NN);
            float v  = g_stats[SIN + 32 + c] * (1.0f / NN) - m * m;
            float sc = bn_g[c] * rsqrtf(v + 1e-5f);
            s_sc[c] = sc;
            s_sh[c] = bn_b[c] - m * sc;
        }
        __syncthreads();
    }
    for (int i = threadIdx.x; i < CO * CI; i += blockDim.x) {
        float sc = HAS_BN ? s_sc[i % CI] : 1.0f;
        s_wl[i] = wl[i] * sc;
        s_wr[i] = wr[i] * sc;
    }
    if (threadIdx.x < CO) {
        int co = threadIdx.x;
        float b = bl[co];
        if (HAS_BN) {
#pragma unroll
            for (int i = 0; i < CI; i++)
                b += s_sh[i] * (wl[co * CI + i] + wr[co * CI + i]);
        }
        s_bias[co] = b;
        if (!LAST) { s_sum[co] = 0.0f; s_sq[co] = 0.0f; }
    }
    __syncthreads();

    int n = blockIdx.x * blockDim.x + threadIdx.x;
    bool act = (n < NN);

    float out[CO];
#pragma unroll
    for (int c = 0; c < CO; c++) out[c] = 0.0f;

    if (act) {
        float4 xv4[V];
        const float4* xr = x4 + (size_t)n * V;
#pragma unroll
        for (int v = 0; v < V; v++) xv4[v] = xr[v];

        float4 acc[V], acc2[V];                  // dual chains break FADD dep
#pragma unroll
        for (int v = 0; v < V; v++) {
            acc[v]  = make_float4(0.f, 0.f, 0.f, 0.f);
            acc2[v] = make_float4(0.f, 0.f, 0.f, 0.f);
        }

        int deg = min(g_cnt[n], CAP);
        int j = 0;
        for (; j + U <= deg; j += U) {
            int s[U];
#pragma unroll
            for (int u = 0; u < U; u++) s[u] = g_slot[(j + u) * NN + n];
            float4 a[U][V];
#pragma unroll
            for (int u = 0; u < U; u++) {
                const float4* r = x4 + (size_t)s[u] * V;
#pragma unroll
                for (int v = 0; v < V; v++) a[u][v] = r[v];
            }
#pragma unroll
            for (int u = 0; u < U; u++) {
#pragma unroll
                for (int v = 0; v < V; v++) {
                    float4& A = (u & 1) ? acc2[v] : acc[v];
                    A.x += a[u][v].x; A.y += a[u][v].y;
                    A.z += a[u][v].z; A.w += a[u][v].w;
                }
            }
        }
        for (; j < deg; j++) {
            int s0 = g_slot[j * NN + n];
            const float4* r0 = x4 + (size_t)s0 * V;
#pragma unroll
            for (int v = 0; v < V; v++) {
                float4 a0 = r0[v];
                acc[v].x += a0.x; acc[v].y += a0.y;
                acc[v].z += a0.z; acc[v].w += a0.w;
            }
        }
#pragma unroll
        for (int v = 0; v < V; v++) {
            acc[v].x += acc2[v].x; acc[v].y += acc2[v].y;
            acc[v].z += acc2[v].z; acc[v].w += acc2[v].w;
        }

        float cinv = 1.0f / (float)max(deg, 1);
        float av[CI], xv[CI];
        const float* ap = reinterpret_cast<const float*>(acc);
        const float* xp = reinterpret_cast<const float*>(xv4);
#pragma unroll
        for (int i = 0; i < CI; i++) { av[i] = ap[i] * cinv; xv[i] = xp[i]; }

        float ss = 0.0f;
#pragma unroll
        for (int co = 0; co < CO; co++) {
            float t = s_bias[co];
#pragma unroll
            for (int i = 0; i < CI; i++) {
                t = fmaf(av[i], s_wl[co * CI + i], t);
                t = fmaf(xv[i], s_wr[co * CI + i], t);
            }
            out[co] = t;
            ss += t * t;
        }
        float inv = 1.0f / fmaxf(sqrtf(ss), 1e-12f);
#pragma unroll
        for (int co = 0; co < CO; co++)
            out[co] = fmaxf(out[co] * inv, 0.0f);   // L2 norm then relu

        // store (padded, vectorized); pad lanes = 0
        float4* yr4 = reinterpret_cast<float4*>(y) + (size_t)n * W;
#pragma unroll
        for (int w = 0; w < W; w++) {
            float4 o;
            o.x = (4 * w + 0 < CO) ? out[4 * w + 0 < CO ? 4 * w + 0 : 0] : 0.0f;
            o.y = (4 * w + 1 < CO) ? out[4 * w + 1 < CO ? 4 * w + 1 : 0] : 0.0f;
            o.z = (4 * w + 2 < CO) ? out[4 * w + 2 < CO ? 4 * w + 2 : 0] : 0.0f;
            o.w = (4 * w + 3 < CO) ? out[4 * w + 3 < CO ? 4 * w + 3 : 0] : 0.0f;
            yr4[w] = o;
        }
    }

    if (!LAST) {
        // BN batch-stat partial sums: warp shfl -> smem -> global
#pragma unroll
        for (int c = 0; c < CO; c++) {
            float v = out[c];
            float q = v * v;
#pragma unroll
            for (int off = 16; off; off >>= 1) {
                v += __shfl_xor_sync(0xffffffffu, v, off);
                q += __shfl_xor_sync(0xffffffffu, q, off);
            }
            if ((threadIdx.x & 31) == 0) {
                atomicAdd(&s_sum[c], v);
                atomicAdd(&s_sq[c], q);
            }
        }
        __syncthreads();
        if (threadIdx.x < CO) {
            atomicAdd(&g_stats[SOUT + threadIdx.x], s_sum[threadIdx.x]);
            atomicAdd(&g_stats[SOUT + 32 + threadIdx.x], s_sq[threadIdx.x]);
        }
    }
}

// ---------------- launch ----------------------------------------------------
extern "C" void kernel_launch(void* const* d_in, const int* in_sizes, int n_in,
                              void* d_out, int out_size) {
    const float* x   = (const float*)d_in[0];
    const int*   ei  = (const int*)d_in[1];     // int32 edge_index (JAX x64 off)
    const float* w1l = (const float*)d_in[2];
    const float* b1l = (const float*)d_in[3];
    const float* w1r = (const float*)d_in[4];
    const float* w2l = (const float*)d_in[5];
    const float* b2l = (const float*)d_in[6];
    const float* w2r = (const float*)d_in[7];
    const float* w3l = (const float*)d_in[8];
    const float* b3l = (const float*)d_in[9];
    const float* w3r = (const float*)d_in[10];
    const float* w4l = (const float*)d_in[11];
    const float* b4l = (const float*)d_in[12];
    const float* w4r = (const float*)d_in[13];
    const float* g1  = (const float*)d_in[14];
    const float* be1 = (const float*)d_in[15];
    const float* g2  = (const float*)d_in[16];
    const float* be2 = (const float*)d_in[17];
    const float* g3  = (const float*)d_in[18];
    const float* be3 = (const float*)d_in[19];
    float* out = (float*)d_out;

    void *p_cnt, *p_stats, *p_bufA, *p_bufB;
    cudaGetSymbolAddress(&p_cnt, g_cnt);
    cudaGetSymbolAddress(&p_stats, g_stats);
    cudaGetSymbolAddress(&p_bufA, g_bufA4);
    cudaGetSymbolAddress(&p_bufB, g_bufB4);
    float* bufA = (float*)p_bufA;
    float* bufB = (float*)p_bufB;

    const int TB = 256;
    const int gridE = (EE + TB - 1) / TB;
    const int gridN = (NN + TB - 1) / TB;

    // bucket build (single pass)
    cudaMemsetAsync(p_cnt, 0, NN * sizeof(int));
    cudaMemsetAsync(p_stats, 0, 192 * sizeof(float));
    k_fill<<<gridE, TB>>>(ei);

    // L1: 4 -> 6 (pad 8), no input BN
    node_kernel<4, 6, 4, 8, false, false, 0, 0>
        <<<gridN, TB>>>((const float4*)x, w1l, b1l, w1r, nullptr, nullptr, bufA);

    // L2: 6 (pad 8) -> 8, BN1 folded
    node_kernel<6, 8, 8, 8, false, true, 0, 64>
        <<<gridN, TB>>>((const float4*)bufA, w2l, b2l, w2r, g1, be1, bufB);

    // L3: 8 -> 16, BN2 folded
    node_kernel<8, 16, 8, 16, false, true, 64, 128>
        <<<gridN, TB>>>((const float4*)bufB, w3l, b3l, w3r, g2, be2, bufA);

    // L4: 16 -> 32, BN3 folded, final relu straight to d_out
    node_kernel<16, 32, 16, 32, true, true, 128, 0>
        <<<gridN, TB>>>((const float4*)bufA, w4l, b4l, w4r, g3, be3, out);
}